// round 1
// baseline (speedup 1.0000x reference)
#include <cuda_runtime.h>

#define N_USERS 100000
#define N_ITEMS 50000
#define N_NODES (N_USERS + N_ITEMS)
#define EMB_DIM 64
#define N_INTER 1500000
#define BATCH 4096

// ---- scratch: __device__ globals (no allocation allowed) ----
__device__ float g_rep [N_NODES * EMB_DIM];   // ping
__device__ float g_rep2[N_NODES * EMB_DIM];   // pong
__device__ float g_acc [N_NODES * EMB_DIM];   // layer-sum accumulator
__device__ float g_dinv[N_NODES];
__device__ int   g_deg [N_NODES];

// ---------------- degree / normalization ----------------
__global__ void k_zero_deg() {
    int i = blockIdx.x * blockDim.x + threadIdx.x;
    if (i < N_NODES) g_deg[i] = 0;
}

__global__ void k_count(const int* __restrict__ eu, const int* __restrict__ ei) {
    int e = blockIdx.x * blockDim.x + threadIdx.x;
    if (e < N_INTER) {
        atomicAdd(&g_deg[eu[e]], 1);
        atomicAdd(&g_deg[N_USERS + ei[e]], 1);
    }
}

__global__ void k_dinv() {
    int i = blockIdx.x * blockDim.x + threadIdx.x;
    if (i < N_NODES) {
        int d = g_deg[i];
        g_dinv[i] = (d > 0) ? rsqrtf((float)d) : 1.0f;
    }
}

// ---------------- init / zero / accumulate (float4 passes) ----------------
#define NELEM4 (N_NODES * EMB_DIM / 4)

__global__ void k_init(const float* __restrict__ emb) {
    int i = blockIdx.x * blockDim.x + threadIdx.x;
    if (i < NELEM4) {
        float4 v = ((const float4*)emb)[i];
        ((float4*)g_rep)[i] = v;
        ((float4*)g_acc)[i] = v;
    }
}

// zero the *output* buffer of the upcoming spmm. flip=0 -> out is g_rep2
__global__ void k_zero_out(int flip) {
    float4* p = (float4*)(flip ? g_rep : g_rep2);
    int i = blockIdx.x * blockDim.x + threadIdx.x;
    if (i < NELEM4) p[i] = make_float4(0.f, 0.f, 0.f, 0.f);
}

// acc += just-produced output buffer
__global__ void k_acc_add(int flip) {
    const float4* p = (const float4*)(flip ? g_rep : g_rep2);
    int i = blockIdx.x * blockDim.x + threadIdx.x;
    if (i < NELEM4) {
        float4 a = ((float4*)g_acc)[i];
        float4 v = p[i];
        a.x += v.x; a.y += v.y; a.z += v.z; a.w += v.w;
        ((float4*)g_acc)[i] = a;
    }
}

// ---------------- SpMM: one warp per undirected edge ----------------
// lanes 0-15:  gather user row (float4 each), scatter-add into item row
// lanes 16-31: gather item row,               scatter-add into user row
__global__ void k_spmm(const int* __restrict__ eu, const int* __restrict__ ei, int flip) {
    const float* __restrict__ rin = flip ? g_rep2 : g_rep;
    float* __restrict__ rout = flip ? g_rep : g_rep2;

    int w = blockIdx.x * (blockDim.x >> 5) + (threadIdx.x >> 5);
    if (w >= N_INTER) return;
    int lane = threadIdx.x & 31;

    int u = eu[w];
    int v = N_USERS + ei[w];
    float nrm = g_dinv[u] * g_dinv[v];

    int half = lane >> 4;        // 0: u->v, 1: v->u
    int j    = lane & 15;        // float4 index within the 64-dim row
    int srow = half ? v : u;
    int drow = half ? u : v;

    float4 val = *((const float4*)(rin + (size_t)srow * EMB_DIM) + j);
    float4 sv  = make_float4(val.x * nrm, val.y * nrm, val.z * nrm, val.w * nrm);

    float* dp = rout + (size_t)drow * EMB_DIM + j * 4;
    asm volatile("red.global.add.v4.f32 [%0], {%1, %2, %3, %4};"
                 :: "l"(dp), "f"(sv.x), "f"(sv.y), "f"(sv.z), "f"(sv.w)
                 : "memory");
}

// ---------------- epilogue: batch gather + L2 norm ----------------
// one 32-thread block per batch element; lane handles 2 dims (float2)
__global__ void k_gather(const float* __restrict__ emb,
                         const int* __restrict__ users,
                         const int* __restrict__ pos,
                         const int* __restrict__ neg,
                         float* __restrict__ out) {
    int b = blockIdx.x;
    int lane = threadIdx.x;           // 0..31

    int u = users[b];
    int p = N_USERS + pos[b];
    int n = N_USERS + neg[b];

    const float2* acc2 = (const float2*)g_acc;
    const float2* emb2 = (const float2*)emb;

    float2* ou = (float2*)(out);                        // users_r   [BATCH,64]
    float2* op = (float2*)(out + (size_t)BATCH * 64);   // pos_items_r
    float2* on = (float2*)(out + (size_t)2 * BATCH * 64); // neg_items_r
    float*  ol = out + (size_t)3 * BATCH * 64;          // l2_norm_sq [BATCH]

    const float s = 0.25f;  // mean over (L+1)=4 layer reps

    float2 a;
    a = acc2[(size_t)u * 32 + lane]; ou[(size_t)b * 32 + lane] = make_float2(a.x * s, a.y * s);
    a = acc2[(size_t)p * 32 + lane]; op[(size_t)b * 32 + lane] = make_float2(a.x * s, a.y * s);
    a = acc2[(size_t)n * 32 + lane]; on[(size_t)b * 32 + lane] = make_float2(a.x * s, a.y * s);

    float2 e1 = emb2[(size_t)u * 32 + lane];
    float2 e2 = emb2[(size_t)p * 32 + lane];
    float2 e3 = emb2[(size_t)n * 32 + lane];
    float part = e1.x * e1.x + e1.y * e1.y
               + e2.x * e2.x + e2.y * e2.y
               + e3.x * e3.x + e3.y * e3.y;
    #pragma unroll
    for (int off = 16; off; off >>= 1)
        part += __shfl_down_sync(0xffffffffu, part, off);
    if (lane == 0) ol[b] = part;
}

// ---------------- launcher ----------------
extern "C" void kernel_launch(void* const* d_in, const int* in_sizes, int n_in,
                              void* d_out, int out_size) {
    const float* emb   = (const float*)d_in[0];
    const int*   eu    = (const int*)d_in[1];
    const int*   ei    = (const int*)d_in[2];
    const int*   users = (const int*)d_in[3];
    const int*   pos   = (const int*)d_in[4];
    const int*   neg   = (const int*)d_in[5];
    float* out = (float*)d_out;
    (void)in_sizes; (void)n_in; (void)out_size;

    const int T = 256;

    // degrees + normalization
    k_zero_deg<<<(N_NODES + T - 1) / T, T>>>();
    k_count   <<<(N_INTER + T - 1) / T, T>>>(eu, ei);
    k_dinv    <<<(N_NODES + T - 1) / T, T>>>();

    // rep0 = acc = embedding
    k_init<<<(NELEM4 + T - 1) / T, T>>>(emb);

    // 3 propagation layers, ping-pong buffers; flip sequence 0,1,0
    const int spmm_grid = (N_INTER + (T / 32) - 1) / (T / 32);
    int flips[3] = {0, 1, 0};
    for (int l = 0; l < 3; l++) {
        int f = flips[l];
        k_zero_out<<<(NELEM4 + T - 1) / T, T>>>(f);
        k_spmm    <<<spmm_grid, T>>>(eu, ei, f);
        k_acc_add <<<(NELEM4 + T - 1) / T, T>>>(f);
    }

    // epilogue
    k_gather<<<BATCH, 32>>>(emb, users, pos, neg, out);
}

// round 2
// speedup vs baseline: 1.8844x; 1.8844x over previous
#include <cuda_runtime.h>

#define N_USERS 100000
#define N_ITEMS 50000
#define N_NODES (N_USERS + N_ITEMS)
#define EMB_DIM 64
#define N_INTER 1500000
#define N_EDGES (2 * N_INTER)          // directed
#define BATCH 4096

// ---- scratch: __device__ globals (no allocation allowed) ----
__device__ float g_q1[N_NODES * EMB_DIM];   // q_l = D^-1/2 * rep_l (pre-scaled space)
__device__ float g_q2[N_NODES * EMB_DIM];
__device__ float g_q3[N_NODES * EMB_DIM];
__device__ int   g_col[N_EDGES];            // CSR (by destination): source node ids
__device__ int   g_off[N_NODES + 1];        // CSR row offsets
__device__ int   g_cur[N_NODES];            // fill cursors
__device__ int   g_deg[N_NODES];
__device__ float g_dinv [N_NODES];          // deg^-1/2 (1 if deg==0)
__device__ float g_dinv2[N_NODES];          // dinv*dinv

// ---------------- degrees ----------------
__global__ void k_zero_deg() {
    int i = blockIdx.x * blockDim.x + threadIdx.x;
    if (i < N_NODES) g_deg[i] = 0;
}

__global__ void k_count(const int* __restrict__ eu, const int* __restrict__ ei) {
    int e = blockIdx.x * blockDim.x + threadIdx.x;
    if (e < N_INTER) {
        atomicAdd(&g_deg[eu[e]], 1);
        atomicAdd(&g_deg[N_USERS + ei[e]], 1);
    }
}

__global__ void k_dinv() {
    int i = blockIdx.x * blockDim.x + threadIdx.x;
    if (i < N_NODES) {
        int d = g_deg[i];
        float r = (d > 0) ? rsqrtf((float)d) : 1.0f;
        g_dinv[i] = r;
        g_dinv2[i] = r * r;
    }
}

// ---------------- single-block exclusive scan over degrees ----------------
__global__ void k_scan() {
    __shared__ int wsum[32];
    __shared__ int carry;
    int tid = threadIdx.x, lane = tid & 31, wid = tid >> 5;
    if (tid == 0) carry = 0;
    __syncthreads();
    for (int base = 0; base < N_NODES; base += 1024) {
        int i = base + tid;
        int v = (i < N_NODES) ? g_deg[i] : 0;
        int x = v;
        #pragma unroll
        for (int o = 1; o < 32; o <<= 1) {
            int y = __shfl_up_sync(0xffffffffu, x, o);
            if (lane >= o) x += y;
        }
        if (lane == 31) wsum[wid] = x;
        __syncthreads();
        if (wid == 0) {
            int w = wsum[lane];
            #pragma unroll
            for (int o = 1; o < 32; o <<= 1) {
                int y = __shfl_up_sync(0xffffffffu, w, o);
                if (lane >= o) w += y;
            }
            wsum[lane] = w;                  // inclusive scan of warp sums
        }
        __syncthreads();
        int warp_prefix = (wid == 0) ? 0 : wsum[wid - 1];
        int excl = carry + warp_prefix + (x - v);
        if (i < N_NODES) { g_off[i] = excl; g_cur[i] = excl; }
        int chunk_total = wsum[31];
        __syncthreads();                     // all reads of carry/wsum done
        if (tid == 0) carry += chunk_total;
        __syncthreads();
    }
    if (threadIdx.x == 0) g_off[N_NODES] = carry;
}

// ---------------- CSR fill (order within a row irrelevant) ----------------
__global__ void k_fill(const int* __restrict__ eu, const int* __restrict__ ei) {
    int e = blockIdx.x * blockDim.x + threadIdx.x;
    if (e >= N_INTER) return;
    int u = eu[e];
    int v = N_USERS + ei[e];
    int p1 = atomicAdd(&g_cur[v], 1); g_col[p1] = u;   // u -> v
    int p2 = atomicAdd(&g_cur[u], 1); g_col[p2] = v;   // v -> u
}

// ---------------- gather-only SpMM in q-space ----------------
// one warp per destination node; 2 edge-groups x 16 lanes x float4
// LAYER 1: q1[d] = dinv2[d] * sum_src dinv[src]*emb[src]
// LAYER>1: q_{l}[d] = dinv2[d] * sum_src q_{l-1}[src]
template <int LAYER>
__global__ void k_prop(const float* __restrict__ emb) {
    const float* __restrict__ qin =
        (LAYER == 1) ? emb : (LAYER == 2 ? g_q1 : g_q2);
    float* __restrict__ qout =
        (LAYER == 1) ? g_q1 : (LAYER == 2 ? g_q2 : g_q3);

    int w = blockIdx.x * (blockDim.x >> 5) + (threadIdx.x >> 5);
    if (w >= N_NODES) return;
    int lane = threadIdx.x & 31;
    int g = lane >> 4;           // edge group 0/1
    int j = lane & 15;           // float4 index within 64-dim row

    int s = g_off[w];
    int e = g_off[w + 1];

    float4 acc = make_float4(0.f, 0.f, 0.f, 0.f);
    #pragma unroll 4
    for (int p = s + g; p < e; p += 2) {
        int src = g_col[p];
        float4 v = ((const float4*)(qin + (size_t)src * EMB_DIM))[j];
        if (LAYER == 1) {
            float sc = g_dinv[src];
            acc.x += v.x * sc; acc.y += v.y * sc;
            acc.z += v.z * sc; acc.w += v.w * sc;
        } else {
            acc.x += v.x; acc.y += v.y; acc.z += v.z; acc.w += v.w;
        }
    }
    // combine the two edge groups (lane i gets lane i+16's partial, same j)
    acc.x += __shfl_down_sync(0xffffffffu, acc.x, 16);
    acc.y += __shfl_down_sync(0xffffffffu, acc.y, 16);
    acc.z += __shfl_down_sync(0xffffffffu, acc.z, 16);
    acc.w += __shfl_down_sync(0xffffffffu, acc.w, 16);
    if (g == 0) {
        float d2 = g_dinv2[w];
        ((float4*)(qout + (size_t)w * EMB_DIM))[j] =
            make_float4(acc.x * d2, acc.y * d2, acc.z * d2, acc.w * d2);
    }
}

// ---------------- epilogue: batch gather + L2 norm ----------------
// rep_l = q_l / dinv  ->  final = 0.25*(emb + (q1+q2+q3)/dinv)
__global__ void k_out(const float* __restrict__ emb,
                      const int* __restrict__ users,
                      const int* __restrict__ pos,
                      const int* __restrict__ neg,
                      float* __restrict__ out) {
    int b = blockIdx.x;
    int lane = threadIdx.x;              // 0..31, each handles float2

    int rows[3];
    rows[0] = users[b];
    rows[1] = N_USERS + pos[b];
    rows[2] = N_USERS + neg[b];

    const float2* emb2 = (const float2*)emb;
    const float2* q1 = (const float2*)g_q1;
    const float2* q2 = (const float2*)g_q2;
    const float2* q3 = (const float2*)g_q3;

    float l2 = 0.f;
    #pragma unroll
    for (int t = 0; t < 3; t++) {
        int r = rows[t];
        size_t idx = (size_t)r * 32 + lane;
        float2 e = emb2[idx];
        float2 a = q1[idx];
        float2 bq = q2[idx];
        float2 c = q3[idx];
        float inv = 1.0f / g_dinv[r];
        float2 res;
        res.x = 0.25f * (e.x + (a.x + bq.x + c.x) * inv);
        res.y = 0.25f * (e.y + (a.y + bq.y + c.y) * inv);
        float2* dst = (float2*)(out + (size_t)t * BATCH * EMB_DIM);
        dst[(size_t)b * 32 + lane] = res;
        l2 += e.x * e.x + e.y * e.y;
    }
    #pragma unroll
    for (int off = 16; off; off >>= 1)
        l2 += __shfl_down_sync(0xffffffffu, l2, off);
    if (lane == 0) out[(size_t)3 * BATCH * EMB_DIM + b] = l2;
}

// ---------------- launcher ----------------
extern "C" void kernel_launch(void* const* d_in, const int* in_sizes, int n_in,
                              void* d_out, int out_size) {
    const float* emb   = (const float*)d_in[0];
    const int*   eu    = (const int*)d_in[1];
    const int*   ei    = (const int*)d_in[2];
    const int*   users = (const int*)d_in[3];
    const int*   pos   = (const int*)d_in[4];
    const int*   neg   = (const int*)d_in[5];
    float* out = (float*)d_out;
    (void)in_sizes; (void)n_in; (void)out_size;

    const int T = 256;

    k_zero_deg<<<(N_NODES + T - 1) / T, T>>>();
    k_count   <<<(N_INTER + T - 1) / T, T>>>(eu, ei);
    k_dinv    <<<(N_NODES + T - 1) / T, T>>>();
    k_scan    <<<1, 1024>>>();
    k_fill    <<<(N_INTER + T - 1) / T, T>>>(eu, ei);

    const int prop_grid = (N_NODES + (T / 32) - 1) / (T / 32);
    k_prop<1><<<prop_grid, T>>>(emb);
    k_prop<2><<<prop_grid, T>>>(emb);
    k_prop<3><<<prop_grid, T>>>(emb);

    k_out<<<BATCH, 32>>>(emb, users, pos, neg, out);
}

// round 3
// speedup vs baseline: 2.5669x; 1.3622x over previous
#include <cuda_runtime.h>

#define N_USERS 100000
#define N_ITEMS 50000
#define N_NODES (N_USERS + N_ITEMS)
#define EMB_DIM 64
#define N_INTER 1500000
#define N_EDGES (2 * N_INTER)          // directed
#define BATCH 4096

#define SCAN_T 1024
#define SCAN_NBLK ((N_NODES + SCAN_T - 1) / SCAN_T)   // 147

// ---- scratch: __device__ globals (no allocation allowed) ----
__device__ float g_q1[N_NODES * EMB_DIM];   // q_l = D^-1/2 * rep_l (pre-scaled space)
__device__ float g_q2[N_NODES * EMB_DIM];
__device__ float g_q3[N_NODES * EMB_DIM];
__device__ int   g_col[N_EDGES];            // CSR (by destination): source node ids
__device__ int   g_off[N_NODES + 1];        // CSR row offsets
__device__ int   g_cur[N_NODES];            // fill cursors
__device__ int   g_deg[N_NODES];
__device__ int   g_bsum[SCAN_NBLK];         // per-block scan totals
__device__ float g_dinv [N_NODES];          // deg^-1/2 (1 if deg==0)
__device__ float g_dinv2[N_NODES];          // dinv*dinv

// ---------------- degrees ----------------
__global__ void k_zero_deg() {
    int i = blockIdx.x * blockDim.x + threadIdx.x;
    if (i < N_NODES) g_deg[i] = 0;
}

__global__ void k_count(const int* __restrict__ eu, const int* __restrict__ ei) {
    int e = blockIdx.x * blockDim.x + threadIdx.x;
    if (e < N_INTER) {
        atomicAdd(&g_deg[eu[e]], 1);
        atomicAdd(&g_deg[N_USERS + ei[e]], 1);
    }
}

__global__ void k_dinv() {
    int i = blockIdx.x * blockDim.x + threadIdx.x;
    if (i < N_NODES) {
        int d = g_deg[i];
        float r = (d > 0) ? rsqrtf((float)d) : 1.0f;
        g_dinv[i] = r;
        g_dinv2[i] = r * r;
    }
}

// ---------------- two-level parallel exclusive scan over degrees ----------------
// pass 1: per-block exclusive scan -> g_off (partial), block total -> g_bsum
__global__ void k_scan1() {
    __shared__ int wsum[32];
    int tid = threadIdx.x, lane = tid & 31, wid = tid >> 5;
    int i = blockIdx.x * SCAN_T + tid;
    int v = (i < N_NODES) ? g_deg[i] : 0;
    int x = v;
    #pragma unroll
    for (int o = 1; o < 32; o <<= 1) {
        int y = __shfl_up_sync(0xffffffffu, x, o);
        if (lane >= o) x += y;
    }
    if (lane == 31) wsum[wid] = x;
    __syncthreads();
    if (wid == 0) {
        int w = wsum[lane];
        #pragma unroll
        for (int o = 1; o < 32; o <<= 1) {
            int y = __shfl_up_sync(0xffffffffu, w, o);
            if (lane >= o) w += y;
        }
        wsum[lane] = w;                 // inclusive scan of warp sums
    }
    __syncthreads();
    int warp_prefix = (wid == 0) ? 0 : wsum[wid - 1];
    if (i < N_NODES) g_off[i] = warp_prefix + (x - v);   // block-local exclusive
    if (tid == SCAN_T - 1) g_bsum[blockIdx.x] = wsum[31];
}

// pass 2: single small block scans the block totals (exclusive, in place)
__global__ void k_scan2() {
    __shared__ int wsum[32];
    int tid = threadIdx.x, lane = tid & 31, wid = tid >> 5;   // 256 threads, 8 warps
    int v = (tid < SCAN_NBLK) ? g_bsum[tid] : 0;
    int x = v;
    #pragma unroll
    for (int o = 1; o < 32; o <<= 1) {
        int y = __shfl_up_sync(0xffffffffu, x, o);
        if (lane >= o) x += y;
    }
    if (lane == 31) wsum[wid] = x;
    __syncthreads();
    if (wid == 0 && lane < 8) {
        int w = wsum[lane];
        #pragma unroll
        for (int o = 1; o < 8; o <<= 1) {
            int y = __shfl_up_sync(0xffu, w, o);
            if (lane >= o) w += y;
        }
        wsum[lane] = w;
    }
    __syncthreads();
    int warp_prefix = (wid == 0) ? 0 : wsum[wid - 1];
    if (tid < SCAN_NBLK) g_bsum[tid] = warp_prefix + (x - v);  // exclusive
}

// pass 3: add block offsets, init cursors, set sentinel
__global__ void k_scan3() {
    int i = blockIdx.x * blockDim.x + threadIdx.x;
    if (i < N_NODES) {
        int o = g_off[i] + g_bsum[i / SCAN_T];
        g_off[i] = o;
        g_cur[i] = o;
    }
    if (i == 0) g_off[N_NODES] = N_EDGES;   // total is statically known
}

// ---------------- CSR fill (order within a row irrelevant) ----------------
__global__ void k_fill(const int* __restrict__ eu, const int* __restrict__ ei) {
    int e = blockIdx.x * blockDim.x + threadIdx.x;
    if (e >= N_INTER) return;
    int u = eu[e];
    int v = N_USERS + ei[e];
    int p1 = atomicAdd(&g_cur[v], 1); g_col[p1] = u;   // u -> v
    int p2 = atomicAdd(&g_cur[u], 1); g_col[p2] = v;   // v -> u
}

// ---------------- gather-only SpMM in q-space ----------------
// one warp per destination node; 2 edge-groups x 16 lanes x float4
// LAYER 1: q1[d] = dinv2[d] * sum_src dinv[src]*emb[src]
// LAYER>1: q_{l}[d] = dinv2[d] * sum_src q_{l-1}[src]
template <int LAYER>
__global__ void k_prop(const float* __restrict__ emb) {
    const float* __restrict__ qin =
        (LAYER == 1) ? emb : (LAYER == 2 ? g_q1 : g_q2);
    float* __restrict__ qout =
        (LAYER == 1) ? g_q1 : (LAYER == 2 ? g_q2 : g_q3);

    int w = blockIdx.x * (blockDim.x >> 5) + (threadIdx.x >> 5);
    if (w >= N_NODES) return;
    int lane = threadIdx.x & 31;
    int g = lane >> 4;           // edge group 0/1
    int j = lane & 15;           // float4 index within 64-dim row

    int s = g_off[w];
    int e = g_off[w + 1];

    float4 acc = make_float4(0.f, 0.f, 0.f, 0.f);
    #pragma unroll 4
    for (int p = s + g; p < e; p += 2) {
        int src = g_col[p];
        float4 v = ((const float4*)(qin + (size_t)src * EMB_DIM))[j];
        if (LAYER == 1) {
            float sc = g_dinv[src];
            acc.x += v.x * sc; acc.y += v.y * sc;
            acc.z += v.z * sc; acc.w += v.w * sc;
        } else {
            acc.x += v.x; acc.y += v.y; acc.z += v.z; acc.w += v.w;
        }
    }
    // combine the two edge groups (lane i gets lane i+16's partial, same j)
    acc.x += __shfl_down_sync(0xffffffffu, acc.x, 16);
    acc.y += __shfl_down_sync(0xffffffffu, acc.y, 16);
    acc.z += __shfl_down_sync(0xffffffffu, acc.z, 16);
    acc.w += __shfl_down_sync(0xffffffffu, acc.w, 16);
    if (g == 0) {
        float d2 = g_dinv2[w];
        ((float4*)(qout + (size_t)w * EMB_DIM))[j] =
            make_float4(acc.x * d2, acc.y * d2, acc.z * d2, acc.w * d2);
    }
}

// ---------------- epilogue: batch gather + L2 norm ----------------
// rep_l = q_l / dinv  ->  final = 0.25*(emb + (q1+q2+q3)/dinv)
__global__ void k_out(const float* __restrict__ emb,
                      const int* __restrict__ users,
                      const int* __restrict__ pos,
                      const int* __restrict__ neg,
                      float* __restrict__ out) {
    int b = blockIdx.x;
    int lane = threadIdx.x;              // 0..31, each handles float2

    int rows[3];
    rows[0] = users[b];
    rows[1] = N_USERS + pos[b];
    rows[2] = N_USERS + neg[b];

    const float2* emb2 = (const float2*)emb;
    const float2* q1 = (const float2*)g_q1;
    const float2* q2 = (const float2*)g_q2;
    const float2* q3 = (const float2*)g_q3;

    float l2 = 0.f;
    #pragma unroll
    for (int t = 0; t < 3; t++) {
        int r = rows[t];
        size_t idx = (size_t)r * 32 + lane;
        float2 e = emb2[idx];
        float2 a = q1[idx];
        float2 bq = q2[idx];
        float2 c = q3[idx];
        float inv = 1.0f / g_dinv[r];
        float2 res;
        res.x = 0.25f * (e.x + (a.x + bq.x + c.x) * inv);
        res.y = 0.25f * (e.y + (a.y + bq.y + c.y) * inv);
        float2* dst = (float2*)(out + (size_t)t * BATCH * EMB_DIM);
        dst[(size_t)b * 32 + lane] = res;
        l2 += e.x * e.x + e.y * e.y;
    }
    #pragma unroll
    for (int off = 16; off; off >>= 1)
        l2 += __shfl_down_sync(0xffffffffu, l2, off);
    if (lane == 0) out[(size_t)3 * BATCH * EMB_DIM + b] = l2;
}

// ---------------- launcher ----------------
extern "C" void kernel_launch(void* const* d_in, const int* in_sizes, int n_in,
                              void* d_out, int out_size) {
    const float* emb   = (const float*)d_in[0];
    const int*   eu    = (const int*)d_in[1];
    const int*   ei    = (const int*)d_in[2];
    const int*   users = (const int*)d_in[3];
    const int*   pos   = (const int*)d_in[4];
    const int*   neg   = (const int*)d_in[5];
    float* out = (float*)d_out;
    (void)in_sizes; (void)n_in; (void)out_size;

    const int T = 256;

    k_zero_deg<<<(N_NODES + T - 1) / T, T>>>();
    k_count   <<<(N_INTER + T - 1) / T, T>>>(eu, ei);
    k_dinv    <<<(N_NODES + T - 1) / T, T>>>();
    k_scan1   <<<SCAN_NBLK, SCAN_T>>>();
    k_scan2   <<<1, 256>>>();
    k_scan3   <<<(N_NODES + T - 1) / T, T>>>();
    k_fill    <<<(N_INTER + T - 1) / T, T>>>(eu, ei);

    const int prop_grid = (N_NODES + (T / 32) - 1) / (T / 32);
    k_prop<1><<<prop_grid, T>>>(emb);
    k_prop<2><<<prop_grid, T>>>(emb);
    k_prop<3><<<prop_grid, T>>>(emb);

    k_out<<<BATCH, 32>>>(emb, users, pos, neg, out);
}

// round 4
// speedup vs baseline: 2.7381x; 1.0667x over previous
#include <cuda_runtime.h>
#include <cuda_fp16.h>

#define N_USERS 100000
#define N_ITEMS 50000
#define N_NODES (N_USERS + N_ITEMS)
#define EMB_DIM 64
#define N_INTER 1500000
#define N_EDGES (2 * N_INTER)          // directed
#define BATCH 4096

#define SCAN_T 1024
#define SCAN_NBLK ((N_NODES + SCAN_T - 1) / SCAN_T)   // 147

// ---- scratch: __device__ globals (no allocation allowed) ----
__device__ float   g_q1[N_NODES * EMB_DIM];   // fp32 carry (epilogue-accurate)
__device__ float   g_q2[N_NODES * EMB_DIM];
__device__ float   g_q3[N_NODES * EMB_DIM];
__device__ __half2 g_h0[N_NODES * EMB_DIM / 2];  // fp16 gather shadows
__device__ __half2 g_h1[N_NODES * EMB_DIM / 2];
__device__ __half2 g_h2[N_NODES * EMB_DIM / 2];
__device__ int     g_col[N_EDGES];            // CSR (by destination): source ids
__device__ int     g_off[N_NODES + 1];
__device__ int     g_cur[N_NODES];
__device__ int     g_deg[N_NODES];
__device__ int     g_bsum[SCAN_NBLK];
__device__ float   g_dinv [N_NODES];          // deg^-1/2 (1 if deg==0)
__device__ float   g_dinv2[N_NODES];

// ---------------- degrees ----------------
__global__ void k_zero_deg() {
    int i = blockIdx.x * blockDim.x + threadIdx.x;
    if (i < N_NODES) g_deg[i] = 0;
}

__global__ void k_count(const int* __restrict__ eu, const int* __restrict__ ei) {
    int e = blockIdx.x * blockDim.x + threadIdx.x;
    if (e < N_INTER) {
        atomicAdd(&g_deg[eu[e]], 1);
        atomicAdd(&g_deg[N_USERS + ei[e]], 1);
    }
}

// ---------------- two-level scan (+ dinv folded into pass 1) ----------------
__global__ void k_scan1() {
    __shared__ int wsum[32];
    int tid = threadIdx.x, lane = tid & 31, wid = tid >> 5;
    int i = blockIdx.x * SCAN_T + tid;
    int v = (i < N_NODES) ? g_deg[i] : 0;
    if (i < N_NODES) {                       // fold dinv computation here
        float r = (v > 0) ? rsqrtf((float)v) : 1.0f;
        g_dinv[i] = r;
        g_dinv2[i] = r * r;
    }
    int x = v;
    #pragma unroll
    for (int o = 1; o < 32; o <<= 1) {
        int y = __shfl_up_sync(0xffffffffu, x, o);
        if (lane >= o) x += y;
    }
    if (lane == 31) wsum[wid] = x;
    __syncthreads();
    if (wid == 0) {
        int w = wsum[lane];
        #pragma unroll
        for (int o = 1; o < 32; o <<= 1) {
            int y = __shfl_up_sync(0xffffffffu, w, o);
            if (lane >= o) w += y;
        }
        wsum[lane] = w;
    }
    __syncthreads();
    int warp_prefix = (wid == 0) ? 0 : wsum[wid - 1];
    if (i < N_NODES) g_off[i] = warp_prefix + (x - v);   // block-local exclusive
    if (tid == SCAN_T - 1) g_bsum[blockIdx.x] = wsum[31];
}

__global__ void k_scan2() {
    __shared__ int wsum[32];
    int tid = threadIdx.x, lane = tid & 31, wid = tid >> 5;   // 256 threads
    int v = (tid < SCAN_NBLK) ? g_bsum[tid] : 0;
    int x = v;
    #pragma unroll
    for (int o = 1; o < 32; o <<= 1) {
        int y = __shfl_up_sync(0xffffffffu, x, o);
        if (lane >= o) x += y;
    }
    if (lane == 31) wsum[wid] = x;
    __syncthreads();
    if (wid == 0 && lane < 8) {
        int w = wsum[lane];
        #pragma unroll
        for (int o = 1; o < 8; o <<= 1) {
            int y = __shfl_up_sync(0xffu, w, o);
            if (lane >= o) w += y;
        }
        wsum[lane] = w;
    }
    __syncthreads();
    int warp_prefix = (wid == 0) ? 0 : wsum[wid - 1];
    if (tid < SCAN_NBLK) g_bsum[tid] = warp_prefix + (x - v);
}

__global__ void k_scan3() {
    int i = blockIdx.x * blockDim.x + threadIdx.x;
    if (i < N_NODES) {
        int o = g_off[i] + g_bsum[i / SCAN_T];
        g_off[i] = o;
        g_cur[i] = o;
    }
    if (i == 0) g_off[N_NODES] = N_EDGES;
}

// ---------------- h0 = fp16(dinv ⊙ emb)  (layer-1 gather shadow) ----------------
__global__ void k_h0(const float* __restrict__ emb) {
    int i = blockIdx.x * blockDim.x + threadIdx.x;   // over N_NODES*32 half2s
    if (i >= N_NODES * (EMB_DIM / 2)) return;
    int node = i >> 5;                               // EMB_DIM/2 == 32
    float d = g_dinv[node];
    float2 v = ((const float2*)emb)[i];
    g_h0[i] = __floats2half2_rn(v.x * d, v.y * d);
}

// ---------------- CSR fill ----------------
__global__ void k_fill(const int* __restrict__ eu, const int* __restrict__ ei) {
    int e = blockIdx.x * blockDim.x + threadIdx.x;
    if (e >= N_INTER) return;
    int u = eu[e];
    int v = N_USERS + ei[e];
    int p1 = atomicAdd(&g_cur[v], 1); g_col[p1] = u;
    int p2 = atomicAdd(&g_cur[u], 1); g_col[p2] = v;
}

// ---------------- gather SpMM, fp16 in / fp32 out (+fp16 shadow) ----------------
// one warp per destination node; 2 edge-groups x 16 lanes x 8B (4 halves)
// q_l[d] = dinv2[d] * sum_src h_{l-1}[src];  h_l = fp16(q_l)
template <int LAYER>
__global__ void k_prop() {
    const __half2* __restrict__ hin =
        (LAYER == 1) ? g_h0 : (LAYER == 2 ? g_h1 : g_h2);
    float* __restrict__ qout =
        (LAYER == 1) ? g_q1 : (LAYER == 2 ? g_q2 : g_q3);
    __half2* __restrict__ hout =
        (LAYER == 1) ? g_h1 : (LAYER == 2 ? g_h2 : (__half2*)0);

    int w = blockIdx.x * (blockDim.x >> 5) + (threadIdx.x >> 5);
    if (w >= N_NODES) return;
    int lane = threadIdx.x & 31;
    int g = lane >> 4;           // edge group 0/1
    int j = lane & 15;           // 8-byte chunk index within 128B row

    int s = g_off[w];
    int e = g_off[w + 1];

    float4 acc = make_float4(0.f, 0.f, 0.f, 0.f);
    #pragma unroll 4
    for (int p = s + g; p < e; p += 2) {
        int src = g_col[p];
        // row = 32 half2s; lane j reads half2 pair [2j, 2j+1]
        uint2 raw = ((const uint2*)(hin + (size_t)src * 32))[j];
        __half2 a = *(__half2*)&raw.x;
        __half2 b = *(__half2*)&raw.y;
        float2 fa = __half22float2(a);
        float2 fb = __half22float2(b);
        acc.x += fa.x; acc.y += fa.y;
        acc.z += fb.x; acc.w += fb.y;
    }
    acc.x += __shfl_down_sync(0xffffffffu, acc.x, 16);
    acc.y += __shfl_down_sync(0xffffffffu, acc.y, 16);
    acc.z += __shfl_down_sync(0xffffffffu, acc.z, 16);
    acc.w += __shfl_down_sync(0xffffffffu, acc.w, 16);
    if (g == 0) {
        float d2 = g_dinv2[w];
        float4 r = make_float4(acc.x * d2, acc.y * d2, acc.z * d2, acc.w * d2);
        ((float4*)(qout + (size_t)w * EMB_DIM))[j] = r;
        if (LAYER < 3) {
            uint2 packed;
            __half2 ha = __floats2half2_rn(r.x, r.y);
            __half2 hb = __floats2half2_rn(r.z, r.w);
            packed.x = *(unsigned*)&ha;
            packed.y = *(unsigned*)&hb;
            ((uint2*)(hout + (size_t)w * 32))[j] = packed;
        }
    }
}

// ---------------- epilogue (reads fp32 q's) ----------------
__global__ void k_out(const float* __restrict__ emb,
                      const int* __restrict__ users,
                      const int* __restrict__ pos,
                      const int* __restrict__ neg,
                      float* __restrict__ out) {
    int b = blockIdx.x;
    int lane = threadIdx.x;              // 0..31, each handles float2

    int rows[3];
    rows[0] = users[b];
    rows[1] = N_USERS + pos[b];
    rows[2] = N_USERS + neg[b];

    const float2* emb2 = (const float2*)emb;
    const float2* q1 = (const float2*)g_q1;
    const float2* q2 = (const float2*)g_q2;
    const float2* q3 = (const float2*)g_q3;

    float l2 = 0.f;
    #pragma unroll
    for (int t = 0; t < 3; t++) {
        int r = rows[t];
        size_t idx = (size_t)r * 32 + lane;
        float2 e = emb2[idx];
        float2 a = q1[idx];
        float2 bq = q2[idx];
        float2 c = q3[idx];
        float inv = 1.0f / g_dinv[r];
        float2 res;
        res.x = 0.25f * (e.x + (a.x + bq.x + c.x) * inv);
        res.y = 0.25f * (e.y + (a.y + bq.y + c.y) * inv);
        float2* dst = (float2*)(out + (size_t)t * BATCH * EMB_DIM);
        dst[(size_t)b * 32 + lane] = res;
        l2 += e.x * e.x + e.y * e.y;
    }
    #pragma unroll
    for (int off = 16; off; off >>= 1)
        l2 += __shfl_down_sync(0xffffffffu, l2, off);
    if (lane == 0) out[(size_t)3 * BATCH * EMB_DIM + b] = l2;
}

// ---------------- launcher ----------------
extern "C" void kernel_launch(void* const* d_in, const int* in_sizes, int n_in,
                              void* d_out, int out_size) {
    const float* emb   = (const float*)d_in[0];
    const int*   eu    = (const int*)d_in[1];
    const int*   ei    = (const int*)d_in[2];
    const int*   users = (const int*)d_in[3];
    const int*   pos   = (const int*)d_in[4];
    const int*   neg   = (const int*)d_in[5];
    float* out = (float*)d_out;
    (void)in_sizes; (void)n_in; (void)out_size;

    const int T = 256;

    k_zero_deg<<<(N_NODES + T - 1) / T, T>>>();
    k_count   <<<(N_INTER + T - 1) / T, T>>>(eu, ei);
    k_scan1   <<<SCAN_NBLK, SCAN_T>>>();
    k_scan2   <<<1, 256>>>();
    k_scan3   <<<(N_NODES + T - 1) / T, T>>>();
    k_h0      <<<(N_NODES * (EMB_DIM / 2) + T - 1) / T, T>>>(emb);
    k_fill    <<<(N_INTER + T - 1) / T, T>>>(eu, ei);

    const int prop_grid = (N_NODES + (T / 32) - 1) / (T / 32);
    k_prop<1><<<prop_grid, T>>>();
    k_prop<2><<<prop_grid, T>>>();
    k_prop<3><<<prop_grid, T>>>();

    k_out<<<BATCH, 32>>>(emb, users, pos, neg, out);
}

// round 5
// speedup vs baseline: 3.3271x; 1.2151x over previous
#include <cuda_runtime.h>
#include <cuda_fp16.h>

#define N_USERS 100000
#define N_ITEMS 50000
#define N_NODES (N_USERS + N_ITEMS)
#define EMB_DIM 64
#define N_INTER 1500000
#define N_EDGES (2 * N_INTER)          // directed
#define BATCH 4096

#define SCAN_T 1024
#define SCAN_NBLK ((N_NODES + SCAN_T - 1) / SCAN_T)   // 147

// ---- scratch: __device__ globals (no allocation allowed) ----
__device__ __half2 g_h0[N_NODES * EMB_DIM / 2];  // fp16 gather shadows (128B/row)
__device__ __half2 g_h1[N_NODES * EMB_DIM / 2];
__device__ __half2 g_h2[N_NODES * EMB_DIM / 2];
__device__ int     g_col[N_EDGES];               // CSR (by destination): source ids
__device__ int     g_off[N_NODES + 1];
__device__ int     g_cur[N_NODES];
__device__ int     g_deg[N_NODES];
__device__ int     g_bsum[SCAN_NBLK];
__device__ float   g_dinv [N_NODES];             // deg^-1/2 (1 if deg==0)
__device__ float   g_dinv2[N_NODES];

// ---------------- degrees ----------------
__global__ void k_zero_deg() {
    int i = blockIdx.x * blockDim.x + threadIdx.x;
    if (i < N_NODES) g_deg[i] = 0;
}

__global__ void k_count(const int* __restrict__ eu, const int* __restrict__ ei) {
    int e = blockIdx.x * blockDim.x + threadIdx.x;
    if (e < N_INTER) {
        atomicAdd(&g_deg[eu[e]], 1);
        atomicAdd(&g_deg[N_USERS + ei[e]], 1);
    }
}

// ---------------- two-level scan (+ dinv folded into pass 1) ----------------
__global__ void k_scan1() {
    __shared__ int wsum[32];
    int tid = threadIdx.x, lane = tid & 31, wid = tid >> 5;
    int i = blockIdx.x * SCAN_T + tid;
    int v = (i < N_NODES) ? g_deg[i] : 0;
    if (i < N_NODES) {
        float r = (v > 0) ? rsqrtf((float)v) : 1.0f;
        g_dinv[i] = r;
        g_dinv2[i] = r * r;
    }
    int x = v;
    #pragma unroll
    for (int o = 1; o < 32; o <<= 1) {
        int y = __shfl_up_sync(0xffffffffu, x, o);
        if (lane >= o) x += y;
    }
    if (lane == 31) wsum[wid] = x;
    __syncthreads();
    if (wid == 0) {
        int w = wsum[lane];
        #pragma unroll
        for (int o = 1; o < 32; o <<= 1) {
            int y = __shfl_up_sync(0xffffffffu, w, o);
            if (lane >= o) w += y;
        }
        wsum[lane] = w;
    }
    __syncthreads();
    int warp_prefix = (wid == 0) ? 0 : wsum[wid - 1];
    if (i < N_NODES) g_off[i] = warp_prefix + (x - v);
    if (tid == SCAN_T - 1) g_bsum[blockIdx.x] = wsum[31];
}

__global__ void k_scan2() {
    __shared__ int wsum[32];
    int tid = threadIdx.x, lane = tid & 31, wid = tid >> 5;   // 256 threads
    int v = (tid < SCAN_NBLK) ? g_bsum[tid] : 0;
    int x = v;
    #pragma unroll
    for (int o = 1; o < 32; o <<= 1) {
        int y = __shfl_up_sync(0xffffffffu, x, o);
        if (lane >= o) x += y;
    }
    if (lane == 31) wsum[wid] = x;
    __syncthreads();
    if (wid == 0 && lane < 8) {
        int w = wsum[lane];
        #pragma unroll
        for (int o = 1; o < 8; o <<= 1) {
            int y = __shfl_up_sync(0xffu, w, o);
            if (lane >= o) w += y;
        }
        wsum[lane] = w;
    }
    __syncthreads();
    int warp_prefix = (wid == 0) ? 0 : wsum[wid - 1];
    if (tid < SCAN_NBLK) g_bsum[tid] = warp_prefix + (x - v);
}

__global__ void k_scan3() {
    int i = blockIdx.x * blockDim.x + threadIdx.x;
    if (i < N_NODES) {
        int o = g_off[i] + g_bsum[i / SCAN_T];
        g_off[i] = o;
        g_cur[i] = o;
    }
    if (i == 0) g_off[N_NODES] = N_EDGES;
}

// ---------------- h0 = fp16(dinv ⊙ emb) ----------------
__global__ void k_h0(const float* __restrict__ emb) {
    int i = blockIdx.x * blockDim.x + threadIdx.x;   // over N_NODES*32 half2s
    if (i >= N_NODES * (EMB_DIM / 2)) return;
    int node = i >> 5;
    float d = g_dinv[node];
    float2 v = ((const float2*)emb)[i];
    g_h0[i] = __floats2half2_rn(v.x * d, v.y * d);
}

// ---------------- CSR fill ----------------
__global__ void k_fill(const int* __restrict__ eu, const int* __restrict__ ei) {
    int e = blockIdx.x * blockDim.x + threadIdx.x;
    if (e >= N_INTER) return;
    int u = eu[e];
    int v = N_USERS + ei[e];
    int p1 = atomicAdd(&g_cur[v], 1); g_col[p1] = u;
    int p2 = atomicAdd(&g_cur[u], 1); g_col[p2] = v;
}

// ---- shared helper: warp-gather one node's neighbor-sum from an fp16 array ----
// lane layout: g = lane>>3 (4 edge groups), j = lane&7 (16B chunk of 128B row)
// returns 8 fp32 partial sums; lanes 0-7 hold the full sum after reduction.
__device__ __forceinline__ void gather_row(const __half2* __restrict__ hin,
                                           int s, int e, int g, int j,
                                           float acc[8]) {
    #pragma unroll
    for (int k = 0; k < 8; k++) acc[k] = 0.f;
    #pragma unroll 4
    for (int p = s + g; p < e; p += 4) {
        int src = g_col[p];
        uint4 raw = ((const uint4*)(hin + (size_t)src * 32))[j];
        float2 f0 = __half22float2(*(__half2*)&raw.x);
        float2 f1 = __half22float2(*(__half2*)&raw.y);
        float2 f2 = __half22float2(*(__half2*)&raw.z);
        float2 f3 = __half22float2(*(__half2*)&raw.w);
        acc[0] += f0.x; acc[1] += f0.y;
        acc[2] += f1.x; acc[3] += f1.y;
        acc[4] += f2.x; acc[5] += f2.y;
        acc[6] += f3.x; acc[7] += f3.y;
    }
    #pragma unroll
    for (int k = 0; k < 8; k++) {
        acc[k] += __shfl_down_sync(0xffffffffu, acc[k], 16);
        acc[k] += __shfl_down_sync(0xffffffffu, acc[k], 8);
    }
}

// ---------------- layers 1 & 2: full-graph, fp16 in / fp16 out ----------------
// h_l[d] = fp16( dinv2[d] * sum_src h_{l-1}[src] )
template <int LAYER>
__global__ void k_prop() {
    const __half2* __restrict__ hin  = (LAYER == 1) ? g_h0 : g_h1;
    __half2* __restrict__       hout = (LAYER == 1) ? g_h1 : g_h2;

    int w = blockIdx.x * (blockDim.x >> 5) + (threadIdx.x >> 5);
    if (w >= N_NODES) return;
    int lane = threadIdx.x & 31;
    int g = lane >> 3;
    int j = lane & 7;

    int s = g_off[w];
    int e = g_off[w + 1];

    float acc[8];
    gather_row(hin, s, e, g, j, acc);

    if (g == 0) {
        float d2 = g_dinv2[w];
        uint4 packed;
        __half2 h0v = __floats2half2_rn(acc[0] * d2, acc[1] * d2);
        __half2 h1v = __floats2half2_rn(acc[2] * d2, acc[3] * d2);
        __half2 h2v = __floats2half2_rn(acc[4] * d2, acc[5] * d2);
        __half2 h3v = __floats2half2_rn(acc[6] * d2, acc[7] * d2);
        packed.x = *(unsigned*)&h0v; packed.y = *(unsigned*)&h1v;
        packed.z = *(unsigned*)&h2v; packed.w = *(unsigned*)&h3v;
        ((uint4*)(hout + (size_t)w * 32))[j] = packed;
    }
}

// ---------------- epilogue: layer-3 on demand at batch nodes + final mean ----
// one warp per (t, b): t=0 users, 1 pos, 2 neg
__global__ void k_out3(const int* __restrict__ users,
                       const int* __restrict__ pos,
                       const int* __restrict__ neg,
                       const float* __restrict__ emb,
                       float* __restrict__ out) {
    int wid = blockIdx.x * (blockDim.x >> 5) + (threadIdx.x >> 5);
    if (wid >= 3 * BATCH) return;
    int t = wid / BATCH;
    int b = wid - t * BATCH;
    int r = (t == 0) ? users[b]
          : (t == 1) ? N_USERS + pos[b]
                     : N_USERS + neg[b];

    int lane = threadIdx.x & 31;
    int g = lane >> 3;
    int j = lane & 7;

    int s = g_off[r];
    int e = g_off[r + 1];

    float acc[8];
    gather_row(g_h2, s, e, g, j, acc);     // layer-3 neighbor sum

    if (g == 0) {
        float d2 = g_dinv2[r];
        float inv = 1.0f / g_dinv[r];      // = sqrt(deg) (1 if deg==0)

        uint4 rh1 = ((const uint4*)(g_h1 + (size_t)r * 32))[j];
        uint4 rh2 = ((const uint4*)(g_h2 + (size_t)r * 32))[j];
        float h1v[8], h2v[8];
        {
            float2 f;
            f = __half22float2(*(__half2*)&rh1.x); h1v[0] = f.x; h1v[1] = f.y;
            f = __half22float2(*(__half2*)&rh1.y); h1v[2] = f.x; h1v[3] = f.y;
            f = __half22float2(*(__half2*)&rh1.z); h1v[4] = f.x; h1v[5] = f.y;
            f = __half22float2(*(__half2*)&rh1.w); h1v[6] = f.x; h1v[7] = f.y;
            f = __half22float2(*(__half2*)&rh2.x); h2v[0] = f.x; h2v[1] = f.y;
            f = __half22float2(*(__half2*)&rh2.y); h2v[2] = f.x; h2v[3] = f.y;
            f = __half22float2(*(__half2*)&rh2.z); h2v[4] = f.x; h2v[5] = f.y;
            f = __half22float2(*(__half2*)&rh2.w); h2v[6] = f.x; h2v[7] = f.y;
        }
        const float4* er = (const float4*)(emb + (size_t)r * EMB_DIM);
        float4 e0 = er[2 * j];
        float4 e1 = er[2 * j + 1];
        float ev[8] = {e0.x, e0.y, e0.z, e0.w, e1.x, e1.y, e1.z, e1.w};

        float res[8];
        #pragma unroll
        for (int k = 0; k < 8; k++)
            res[k] = 0.25f * (ev[k] + (h1v[k] + h2v[k] + acc[k] * d2) * inv);

        float4* orow = (float4*)(out + ((size_t)t * BATCH + b) * EMB_DIM);
        orow[2 * j]     = make_float4(res[0], res[1], res[2], res[3]);
        orow[2 * j + 1] = make_float4(res[4], res[5], res[6], res[7]);
    }
}

// ---------------- l2 norms of raw embeddings (one warp per b) ----------------
__global__ void k_l2(const int* __restrict__ users,
                     const int* __restrict__ pos,
                     const int* __restrict__ neg,
                     const float* __restrict__ emb,
                     float* __restrict__ out) {
    int b = blockIdx.x * (blockDim.x >> 5) + (threadIdx.x >> 5);
    if (b >= BATCH) return;
    int lane = threadIdx.x & 31;

    int rows[3];
    rows[0] = users[b];
    rows[1] = N_USERS + pos[b];
    rows[2] = N_USERS + neg[b];

    const float2* emb2 = (const float2*)emb;
    float l2 = 0.f;
    #pragma unroll
    for (int t = 0; t < 3; t++) {
        float2 e = emb2[(size_t)rows[t] * 32 + lane];
        l2 += e.x * e.x + e.y * e.y;
    }
    #pragma unroll
    for (int off = 16; off; off >>= 1)
        l2 += __shfl_down_sync(0xffffffffu, l2, off);
    if (lane == 0) out[(size_t)3 * BATCH * EMB_DIM + b] = l2;
}

// ---------------- launcher ----------------
extern "C" void kernel_launch(void* const* d_in, const int* in_sizes, int n_in,
                              void* d_out, int out_size) {
    const float* emb   = (const float*)d_in[0];
    const int*   eu    = (const int*)d_in[1];
    const int*   ei    = (const int*)d_in[2];
    const int*   users = (const int*)d_in[3];
    const int*   pos   = (const int*)d_in[4];
    const int*   neg   = (const int*)d_in[5];
    float* out = (float*)d_out;
    (void)in_sizes; (void)n_in; (void)out_size;

    const int T = 256;

    k_zero_deg<<<(N_NODES + T - 1) / T, T>>>();
    k_count   <<<(N_INTER + T - 1) / T, T>>>(eu, ei);
    k_scan1   <<<SCAN_NBLK, SCAN_T>>>();
    k_scan2   <<<1, 256>>>();
    k_scan3   <<<(N_NODES + T - 1) / T, T>>>();
    k_h0      <<<(N_NODES * (EMB_DIM / 2) + T - 1) / T, T>>>(emb);
    k_fill    <<<(N_INTER + T - 1) / T, T>>>(eu, ei);

    const int prop_grid = (N_NODES + (T / 32) - 1) / (T / 32);
    k_prop<1><<<prop_grid, T>>>();
    k_prop<2><<<prop_grid, T>>>();

    k_out3<<<(3 * BATCH + (T / 32) - 1) / (T / 32), T>>>(users, pos, neg, emb, out);
    k_l2  <<<(BATCH + (T / 32) - 1) / (T / 32), T>>>(users, pos, neg, emb, out);
}

// round 6
// speedup vs baseline: 3.8360x; 1.1530x over previous
#include <cuda_runtime.h>
#include <cuda_fp16.h>

#define N_USERS 100000
#define N_ITEMS 50000
#define N_NODES (N_USERS + N_ITEMS)
#define EMB_DIM 64
#define N_INTER 1500000
#define N_EDGES (2 * N_INTER)          // directed
#define BATCH 4096

#define SCAN_T 1024
#define SCAN_NBLK ((N_NODES + SCAN_T - 1) / SCAN_T)   // 147

// ---- scratch: __device__ globals (no allocation allowed) ----
__device__ __half2 g_h0[N_NODES * EMB_DIM / 2];  // fp16 gather shadows (128B/row)
__device__ __half2 g_h1[N_NODES * EMB_DIM / 2];
__device__ __half2 g_h2[N_NODES * EMB_DIM / 2];
__device__ int     g_col[N_EDGES];               // CSR (by destination): source ids
__device__ int     g_off[N_NODES + 1];
__device__ int     g_cur[N_NODES];
__device__ int     g_deg[N_NODES];
__device__ int     g_bsum[SCAN_NBLK];
__device__ float   g_dinv [N_NODES];             // deg^-1/2 (1 if deg==0)
__device__ float   g_dinv2[N_NODES];

// ---------------- degrees ----------------
__global__ void k_zero_deg() {
    int i = blockIdx.x * blockDim.x + threadIdx.x;
    if (i < N_NODES) g_deg[i] = 0;
}

__global__ void k_count(const int* __restrict__ eu, const int* __restrict__ ei) {
    int e = blockIdx.x * blockDim.x + threadIdx.x;
    if (e < N_INTER) {
        atomicAdd(&g_deg[eu[e]], 1);
        atomicAdd(&g_deg[N_USERS + ei[e]], 1);
    }
}

// ---------------- two-level scan (+ dinv folded into pass 1) ----------------
__global__ void k_scan1() {
    __shared__ int wsum[32];
    int tid = threadIdx.x, lane = tid & 31, wid = tid >> 5;
    int i = blockIdx.x * SCAN_T + tid;
    int v = (i < N_NODES) ? g_deg[i] : 0;
    if (i < N_NODES) {
        float r = (v > 0) ? rsqrtf((float)v) : 1.0f;
        g_dinv[i] = r;
        g_dinv2[i] = r * r;
    }
    int x = v;
    #pragma unroll
    for (int o = 1; o < 32; o <<= 1) {
        int y = __shfl_up_sync(0xffffffffu, x, o);
        if (lane >= o) x += y;
    }
    if (lane == 31) wsum[wid] = x;
    __syncthreads();
    if (wid == 0) {
        int w = wsum[lane];
        #pragma unroll
        for (int o = 1; o < 32; o <<= 1) {
            int y = __shfl_up_sync(0xffffffffu, w, o);
            if (lane >= o) w += y;
        }
        wsum[lane] = w;
    }
    __syncthreads();
    int warp_prefix = (wid == 0) ? 0 : wsum[wid - 1];
    if (i < N_NODES) g_off[i] = warp_prefix + (x - v);
    if (tid == SCAN_T - 1) g_bsum[blockIdx.x] = wsum[31];
}

__global__ void k_scan2() {
    __shared__ int wsum[32];
    int tid = threadIdx.x, lane = tid & 31, wid = tid >> 5;   // 256 threads
    int v = (tid < SCAN_NBLK) ? g_bsum[tid] : 0;
    int x = v;
    #pragma unroll
    for (int o = 1; o < 32; o <<= 1) {
        int y = __shfl_up_sync(0xffffffffu, x, o);
        if (lane >= o) x += y;
    }
    if (lane == 31) wsum[wid] = x;
    __syncthreads();
    if (wid == 0 && lane < 8) {
        int w = wsum[lane];
        #pragma unroll
        for (int o = 1; o < 8; o <<= 1) {
            int y = __shfl_up_sync(0xffu, w, o);
            if (lane >= o) w += y;
        }
        wsum[lane] = w;
    }
    __syncthreads();
    int warp_prefix = (wid == 0) ? 0 : wsum[wid - 1];
    if (tid < SCAN_NBLK) g_bsum[tid] = warp_prefix + (x - v);
}

__global__ void k_scan3() {
    int i = blockIdx.x * blockDim.x + threadIdx.x;
    if (i < N_NODES) {
        int o = g_off[i] + g_bsum[i / SCAN_T];
        g_off[i] = o;
        g_cur[i] = o;
    }
    if (i == 0) g_off[N_NODES] = N_EDGES;
}

// ---------------- h0 = fp16(dinv ⊙ emb) ----------------
__global__ void k_h0(const float* __restrict__ emb) {
    int i = blockIdx.x * blockDim.x + threadIdx.x;   // over N_NODES*32 half2s
    if (i >= N_NODES * (EMB_DIM / 2)) return;
    int node = i >> 5;
    float d = g_dinv[node];
    float2 v = ((const float2*)emb)[i];
    g_h0[i] = __floats2half2_rn(v.x * d, v.y * d);
}

// ---------------- CSR fill ----------------
__global__ void k_fill(const int* __restrict__ eu, const int* __restrict__ ei) {
    int e = blockIdx.x * blockDim.x + threadIdx.x;
    if (e >= N_INTER) return;
    int u = eu[e];
    int v = N_USERS + ei[e];
    int p1 = atomicAdd(&g_cur[v], 1); g_col[p1] = u;
    int p2 = atomicAdd(&g_cur[u], 1); g_col[p2] = v;
}

// ---- accumulate one 16B fp16 chunk into 8 fp32 sums ----
__device__ __forceinline__ void acc16(float acc[8], uint4 raw) {
    float2 f0 = __half22float2(*(__half2*)&raw.x);
    float2 f1 = __half22float2(*(__half2*)&raw.y);
    float2 f2 = __half22float2(*(__half2*)&raw.z);
    float2 f3 = __half22float2(*(__half2*)&raw.w);
    acc[0] += f0.x; acc[1] += f0.y;
    acc[2] += f1.x; acc[3] += f1.y;
    acc[4] += f2.x; acc[5] += f2.y;
    acc[6] += f3.x; acc[7] += f3.y;
}

// ---- gather: 8-lane group sums all neighbor rows; lane j owns 16B chunk j ----
// no cross-lane reduction needed; trip count = full degree (unroll is effective)
__device__ __forceinline__ void gather_node(const __half2* __restrict__ hin,
                                            int s, int e, int j, float acc[8]) {
    #pragma unroll
    for (int k = 0; k < 8; k++) acc[k] = 0.f;
    #pragma unroll 4
    for (int p = s; p < e; p++) {
        int src = g_col[p];                    // group-uniform broadcast load
        uint4 raw = ((const uint4*)(hin + (size_t)src * 32))[j];
        acc16(acc, raw);
    }
}

// ---------------- layers 1 & 2: 4 nodes/warp, 8 lanes/node ----------------
// h_l[d] = fp16( dinv2[d] * sum_src h_{l-1}[src] )
template <int LAYER>
__global__ void k_prop() {
    const __half2* __restrict__ hin  = (LAYER == 1) ? g_h0 : g_h1;
    __half2* __restrict__       hout = (LAYER == 1) ? g_h1 : g_h2;

    int grp = blockIdx.x * (blockDim.x >> 3) + (threadIdx.x >> 3);  // node id
    if (grp >= N_NODES) return;
    int j = threadIdx.x & 7;          // 16B chunk within 128B row

    int s = g_off[grp];
    int e = g_off[grp + 1];

    float acc[8];
    gather_node(hin, s, e, j, acc);

    float d2 = g_dinv2[grp];
    uint4 packed;
    __half2 h0v = __floats2half2_rn(acc[0] * d2, acc[1] * d2);
    __half2 h1v = __floats2half2_rn(acc[2] * d2, acc[3] * d2);
    __half2 h2v = __floats2half2_rn(acc[4] * d2, acc[5] * d2);
    __half2 h3v = __floats2half2_rn(acc[6] * d2, acc[7] * d2);
    packed.x = *(unsigned*)&h0v; packed.y = *(unsigned*)&h1v;
    packed.z = *(unsigned*)&h2v; packed.w = *(unsigned*)&h3v;
    ((uint4*)(hout + (size_t)grp * 32))[j] = packed;
}

// ---------------- epilogue: layer-3 on demand at batch nodes ----------------
// one 8-lane group per (t, b): t=0 users, 1 pos, 2 neg
__global__ void k_out3(const int* __restrict__ users,
                       const int* __restrict__ pos,
                       const int* __restrict__ neg,
                       const float* __restrict__ emb,
                       float* __restrict__ out) {
    int id = blockIdx.x * (blockDim.x >> 3) + (threadIdx.x >> 3);
    if (id >= 3 * BATCH) return;
    int t = id / BATCH;
    int b = id - t * BATCH;
    int r = (t == 0) ? users[b]
          : (t == 1) ? N_USERS + pos[b]
                     : N_USERS + neg[b];

    int j = threadIdx.x & 7;

    int s = g_off[r];
    int e = g_off[r + 1];

    float acc[8];
    gather_node(g_h2, s, e, j, acc);       // layer-3 neighbor sum

    float d2 = g_dinv2[r];
    float inv = 1.0f / g_dinv[r];          // = sqrt(deg) (1 if deg==0)

    uint4 rh1 = ((const uint4*)(g_h1 + (size_t)r * 32))[j];
    uint4 rh2 = ((const uint4*)(g_h2 + (size_t)r * 32))[j];
    float h1v[8], h2v[8];
    {
        float2 f;
        f = __half22float2(*(__half2*)&rh1.x); h1v[0] = f.x; h1v[1] = f.y;
        f = __half22float2(*(__half2*)&rh1.y); h1v[2] = f.x; h1v[3] = f.y;
        f = __half22float2(*(__half2*)&rh1.z); h1v[4] = f.x; h1v[5] = f.y;
        f = __half22float2(*(__half2*)&rh1.w); h1v[6] = f.x; h1v[7] = f.y;
        f = __half22float2(*(__half2*)&rh2.x); h2v[0] = f.x; h2v[1] = f.y;
        f = __half22float2(*(__half2*)&rh2.y); h2v[2] = f.x; h2v[3] = f.y;
        f = __half22float2(*(__half2*)&rh2.z); h2v[4] = f.x; h2v[5] = f.y;
        f = __half22float2(*(__half2*)&rh2.w); h2v[6] = f.x; h2v[7] = f.y;
    }
    const float4* er = (const float4*)(emb + (size_t)r * EMB_DIM);
    float4 e0 = er[2 * j];
    float4 e1 = er[2 * j + 1];
    float ev[8] = {e0.x, e0.y, e0.z, e0.w, e1.x, e1.y, e1.z, e1.w};

    float res[8];
    #pragma unroll
    for (int k = 0; k < 8; k++)
        res[k] = 0.25f * (ev[k] + (h1v[k] + h2v[k] + acc[k] * d2) * inv);

    float4* orow = (float4*)(out + ((size_t)t * BATCH + b) * EMB_DIM);
    orow[2 * j]     = make_float4(res[0], res[1], res[2], res[3]);
    orow[2 * j + 1] = make_float4(res[4], res[5], res[6], res[7]);
}

// ---------------- l2 norms of raw embeddings (one warp per b) ----------------
__global__ void k_l2(const int* __restrict__ users,
                     const int* __restrict__ pos,
                     const int* __restrict__ neg,
                     const float* __restrict__ emb,
                     float* __restrict__ out) {
    int b = blockIdx.x * (blockDim.x >> 5) + (threadIdx.x >> 5);
    if (b >= BATCH) return;
    int lane = threadIdx.x & 31;

    int rows[3];
    rows[0] = users[b];
    rows[1] = N_USERS + pos[b];
    rows[2] = N_USERS + neg[b];

    const float2* emb2 = (const float2*)emb;
    float l2 = 0.f;
    #pragma unroll
    for (int t = 0; t < 3; t++) {
        float2 e = emb2[(size_t)rows[t] * 32 + lane];
        l2 += e.x * e.x + e.y * e.y;
    }
    #pragma unroll
    for (int off = 16; off; off >>= 1)
        l2 += __shfl_down_sync(0xffffffffu, l2, off);
    if (lane == 0) out[(size_t)3 * BATCH * EMB_DIM + b] = l2;
}

// ---------------- launcher ----------------
extern "C" void kernel_launch(void* const* d_in, const int* in_sizes, int n_in,
                              void* d_out, int out_size) {
    const float* emb   = (const float*)d_in[0];
    const int*   eu    = (const int*)d_in[1];
    const int*   ei    = (const int*)d_in[2];
    const int*   users = (const int*)d_in[3];
    const int*   pos   = (const int*)d_in[4];
    const int*   neg   = (const int*)d_in[5];
    float* out = (float*)d_out;
    (void)in_sizes; (void)n_in; (void)out_size;

    const int T = 256;

    k_zero_deg<<<(N_NODES + T - 1) / T, T>>>();
    k_count   <<<(N_INTER + T - 1) / T, T>>>(eu, ei);
    k_scan1   <<<SCAN_NBLK, SCAN_T>>>();
    k_scan2   <<<1, 256>>>();
    k_scan3   <<<(N_NODES + T - 1) / T, T>>>();
    k_h0      <<<(N_NODES * (EMB_DIM / 2) + T - 1) / T, T>>>(emb);
    k_fill    <<<(N_INTER + T - 1) / T, T>>>(eu, ei);

    const int GPB = T / 8;                               // node-groups per block
    k_prop<1><<<(N_NODES + GPB - 1) / GPB, T>>>();
    k_prop<2><<<(N_NODES + GPB - 1) / GPB, T>>>();

    k_out3<<<(3 * BATCH + GPB - 1) / GPB, T>>>(users, pos, neg, emb, out);
    k_l2  <<<(BATCH + (T / 32) - 1) / (T / 32), T>>>(users, pos, neg, emb, out);
}

// round 7
// speedup vs baseline: 3.8737x; 1.0098x over previous
#include <cuda_runtime.h>
#include <cuda_fp16.h>

#define N_USERS 100000
#define N_ITEMS 50000
#define N_NODES (N_USERS + N_ITEMS)
#define EMB_DIM 64
#define N_INTER 1500000
#define N_EDGES (2 * N_INTER)          // directed
#define BATCH 4096

#define SCAN_T 1024
#define SCAN_NBLK ((N_NODES + SCAN_T - 1) / SCAN_T)   // 147

#define T 256
#define FILL_BLOCKS ((N_INTER + T - 1) / T)                      // fill part
#define H0_ELEMS (N_NODES * (EMB_DIM / 2))                       // half2 count
#define H0_BLOCKS ((H0_ELEMS + T - 1) / T)
#define OUT3_BLOCKS (3 * BATCH / (T / 8))                        // 384
#define L2_BLOCKS (BATCH / (T / 8))                              // 128

// ---- scratch: __device__ globals (no allocation allowed) ----
__device__ __half2 g_h0[N_NODES * EMB_DIM / 2];  // fp16 gather shadows (128B/row)
__device__ __half2 g_h1[N_NODES * EMB_DIM / 2];
__device__ __half2 g_h2[N_NODES * EMB_DIM / 2];
__device__ int     g_col[N_EDGES];               // CSR (by destination): source ids
__device__ int     g_off[N_NODES + 1];
__device__ int     g_cur[N_NODES];
__device__ int     g_deg[N_NODES];
__device__ int     g_bsum[SCAN_NBLK];
__device__ float   g_dinv [N_NODES];             // deg^-1/2 (1 if deg==0)
__device__ float   g_dinv2[N_NODES];

// ---------------- degree count (int4: 4 edges per thread) ----------------
__global__ void k_count(const int* __restrict__ eu, const int* __restrict__ ei) {
    int t = blockIdx.x * blockDim.x + threadIdx.x;
    if (t >= N_INTER / 4) return;
    int4 u4 = ((const int4*)eu)[t];
    int4 i4 = ((const int4*)ei)[t];
    atomicAdd(&g_deg[u4.x], 1); atomicAdd(&g_deg[N_USERS + i4.x], 1);
    atomicAdd(&g_deg[u4.y], 1); atomicAdd(&g_deg[N_USERS + i4.y], 1);
    atomicAdd(&g_deg[u4.z], 1); atomicAdd(&g_deg[N_USERS + i4.z], 1);
    atomicAdd(&g_deg[u4.w], 1); atomicAdd(&g_deg[N_USERS + i4.w], 1);
}

// ---------------- two-level scan (+ dinv folded into pass 1) ----------------
__global__ void k_scan1() {
    __shared__ int wsum[32];
    int tid = threadIdx.x, lane = tid & 31, wid = tid >> 5;
    int i = blockIdx.x * SCAN_T + tid;
    int v = (i < N_NODES) ? g_deg[i] : 0;
    if (i < N_NODES) {
        float r = (v > 0) ? rsqrtf((float)v) : 1.0f;
        g_dinv[i] = r;
        g_dinv2[i] = r * r;
    }
    int x = v;
    #pragma unroll
    for (int o = 1; o < 32; o <<= 1) {
        int y = __shfl_up_sync(0xffffffffu, x, o);
        if (lane >= o) x += y;
    }
    if (lane == 31) wsum[wid] = x;
    __syncthreads();
    if (wid == 0) {
        int w = wsum[lane];
        #pragma unroll
        for (int o = 1; o < 32; o <<= 1) {
            int y = __shfl_up_sync(0xffffffffu, w, o);
            if (lane >= o) w += y;
        }
        wsum[lane] = w;
    }
    __syncthreads();
    int warp_prefix = (wid == 0) ? 0 : wsum[wid - 1];
    if (i < N_NODES) g_off[i] = warp_prefix + (x - v);
    if (tid == SCAN_T - 1) g_bsum[blockIdx.x] = wsum[31];
}

__global__ void k_scan2() {
    __shared__ int wsum[32];
    int tid = threadIdx.x, lane = tid & 31, wid = tid >> 5;   // 256 threads
    int v = (tid < SCAN_NBLK) ? g_bsum[tid] : 0;
    int x = v;
    #pragma unroll
    for (int o = 1; o < 32; o <<= 1) {
        int y = __shfl_up_sync(0xffffffffu, x, o);
        if (lane >= o) x += y;
    }
    if (lane == 31) wsum[wid] = x;
    __syncthreads();
    if (wid == 0 && lane < 8) {
        int w = wsum[lane];
        #pragma unroll
        for (int o = 1; o < 8; o <<= 1) {
            int y = __shfl_up_sync(0xffu, w, o);
            if (lane >= o) w += y;
        }
        wsum[lane] = w;
    }
    __syncthreads();
    int warp_prefix = (wid == 0) ? 0 : wsum[wid - 1];
    if (tid < SCAN_NBLK) g_bsum[tid] = warp_prefix + (x - v);
}

__global__ void k_scan3() {
    int i = blockIdx.x * blockDim.x + threadIdx.x;
    if (i < N_NODES) {
        int o = g_off[i] + g_bsum[i / SCAN_T];
        g_off[i] = o;
        g_cur[i] = o;
    }
    if (i == 0) g_off[N_NODES] = N_EDGES;
}

// ---------------- fused CSR-fill + h0 conversion (independent work) --------
// blocks [0, FILL_BLOCKS): CSR fill.  blocks [FILL_BLOCKS, +H0_BLOCKS): h0.
__global__ void k_fill_h0(const int* __restrict__ eu, const int* __restrict__ ei,
                          const float* __restrict__ emb) {
    if (blockIdx.x < FILL_BLOCKS) {
        int e = blockIdx.x * blockDim.x + threadIdx.x;
        if (e >= N_INTER) return;
        int u = eu[e];
        int v = N_USERS + ei[e];
        int p1 = atomicAdd(&g_cur[v], 1); g_col[p1] = u;
        int p2 = atomicAdd(&g_cur[u], 1); g_col[p2] = v;
    } else {
        int i = (blockIdx.x - FILL_BLOCKS) * blockDim.x + threadIdx.x;
        if (i >= H0_ELEMS) return;
        int node = i >> 5;                       // EMB_DIM/2 == 32 half2/row
        float d = g_dinv[node];
        float2 v = ((const float2*)emb)[i];
        g_h0[i] = __floats2half2_rn(v.x * d, v.y * d);
    }
}

// ---- accumulate one 16B fp16 chunk into 8 fp32 sums ----
__device__ __forceinline__ void acc16(float acc[8], uint4 raw) {
    float2 f0 = __half22float2(*(__half2*)&raw.x);
    float2 f1 = __half22float2(*(__half2*)&raw.y);
    float2 f2 = __half22float2(*(__half2*)&raw.z);
    float2 f3 = __half22float2(*(__half2*)&raw.w);
    acc[0] += f0.x; acc[1] += f0.y;
    acc[2] += f1.x; acc[3] += f1.y;
    acc[4] += f2.x; acc[5] += f2.y;
    acc[6] += f3.x; acc[7] += f3.y;
}

// ---- gather: 8-lane group sums all neighbor rows; lane j owns 16B chunk j ----
__device__ __forceinline__ void gather_node(const __half2* __restrict__ hin,
                                            int s, int e, int j, float acc[8]) {
    #pragma unroll
    for (int k = 0; k < 8; k++) acc[k] = 0.f;
    #pragma unroll 8
    for (int p = s; p < e; p++) {
        int src = g_col[p];                    // group-uniform broadcast load
        uint4 raw = ((const uint4*)(hin + (size_t)src * 32))[j];
        acc16(acc, raw);
    }
}

// ---------------- layers 1 & 2: 4 nodes/warp, 8 lanes/node ----------------
template <int LAYER>
__global__ void k_prop() {
    const __half2* __restrict__ hin  = (LAYER == 1) ? g_h0 : g_h1;
    __half2* __restrict__       hout = (LAYER == 1) ? g_h1 : g_h2;

    int grp = blockIdx.x * (blockDim.x >> 3) + (threadIdx.x >> 3);  // node id
    if (grp >= N_NODES) return;
    int j = threadIdx.x & 7;          // 16B chunk within 128B row

    int s = g_off[grp];
    int e = g_off[grp + 1];

    float acc[8];
    gather_node(hin, s, e, j, acc);

    float d2 = g_dinv2[grp];
    uint4 packed;
    __half2 h0v = __floats2half2_rn(acc[0] * d2, acc[1] * d2);
    __half2 h1v = __floats2half2_rn(acc[2] * d2, acc[3] * d2);
    __half2 h2v = __floats2half2_rn(acc[4] * d2, acc[5] * d2);
    __half2 h3v = __floats2half2_rn(acc[6] * d2, acc[7] * d2);
    packed.x = *(unsigned*)&h0v; packed.y = *(unsigned*)&h1v;
    packed.z = *(unsigned*)&h2v; packed.w = *(unsigned*)&h3v;
    ((uint4*)(hout + (size_t)grp * 32))[j] = packed;
}

// ---------------- tail: out3 (layer-3 on demand) + l2 norms, one launch ----
__global__ void k_tail(const int* __restrict__ users,
                       const int* __restrict__ pos,
                       const int* __restrict__ neg,
                       const float* __restrict__ emb,
                       float* __restrict__ out) {
    int j = threadIdx.x & 7;
    if (blockIdx.x < OUT3_BLOCKS) {
        // ---- out3: one 8-lane group per (t, b) ----
        int id = blockIdx.x * (blockDim.x >> 3) + (threadIdx.x >> 3);
        int t = id / BATCH;
        int b = id - t * BATCH;
        int r = (t == 0) ? users[b]
              : (t == 1) ? N_USERS + pos[b]
                         : N_USERS + neg[b];

        int s = g_off[r];
        int e = g_off[r + 1];

        float acc[8];
        gather_node(g_h2, s, e, j, acc);       // layer-3 neighbor sum

        float d2 = g_dinv2[r];
        float inv = 1.0f / g_dinv[r];          // = sqrt(deg) (1 if deg==0)

        uint4 rh1 = ((const uint4*)(g_h1 + (size_t)r * 32))[j];
        uint4 rh2 = ((const uint4*)(g_h2 + (size_t)r * 32))[j];
        float h1v[8], h2v[8];
        {
            float2 f;
            f = __half22float2(*(__half2*)&rh1.x); h1v[0] = f.x; h1v[1] = f.y;
            f = __half22float2(*(__half2*)&rh1.y); h1v[2] = f.x; h1v[3] = f.y;
            f = __half22float2(*(__half2*)&rh1.z); h1v[4] = f.x; h1v[5] = f.y;
            f = __half22float2(*(__half2*)&rh1.w); h1v[6] = f.x; h1v[7] = f.y;
            f = __half22float2(*(__half2*)&rh2.x); h2v[0] = f.x; h2v[1] = f.y;
            f = __half22float2(*(__half2*)&rh2.y); h2v[2] = f.x; h2v[3] = f.y;
            f = __half22float2(*(__half2*)&rh2.z); h2v[4] = f.x; h2v[5] = f.y;
            f = __half22float2(*(__half2*)&rh2.w); h2v[6] = f.x; h2v[7] = f.y;
        }
        const float4* er = (const float4*)(emb + (size_t)r * EMB_DIM);
        float4 e0 = er[2 * j];
        float4 e1 = er[2 * j + 1];
        float ev[8] = {e0.x, e0.y, e0.z, e0.w, e1.x, e1.y, e1.z, e1.w};

        float res[8];
        #pragma unroll
        for (int k = 0; k < 8; k++)
            res[k] = 0.25f * (ev[k] + (h1v[k] + h2v[k] + acc[k] * d2) * inv);

        float4* orow = (float4*)(out + ((size_t)t * BATCH + b) * EMB_DIM);
        orow[2 * j]     = make_float4(res[0], res[1], res[2], res[3]);
        orow[2 * j + 1] = make_float4(res[4], res[5], res[6], res[7]);
    } else {
        // ---- l2: one 8-lane group per b ----
        int b = (blockIdx.x - OUT3_BLOCKS) * (blockDim.x >> 3) + (threadIdx.x >> 3);
        if (b >= BATCH) return;

        int rows[3];
        rows[0] = users[b];
        rows[1] = N_USERS + pos[b];
        rows[2] = N_USERS + neg[b];

        float l2 = 0.f;
        #pragma unroll
        for (int t = 0; t < 3; t++) {
            const float4* er = (const float4*)(emb + (size_t)rows[t] * EMB_DIM);
            float4 a = er[2 * j];
            float4 c = er[2 * j + 1];
            l2 += a.x * a.x + a.y * a.y + a.z * a.z + a.w * a.w
                + c.x * c.x + c.y * c.y + c.z * c.z + c.w * c.w;
        }
        #pragma unroll
        for (int off = 4; off; off >>= 1)
            l2 += __shfl_down_sync(0xffffffffu, l2, off, 8);
        if (j == 0) out[(size_t)3 * BATCH * EMB_DIM + b] = l2;
    }
}

// ---------------- launcher ----------------
extern "C" void kernel_launch(void* const* d_in, const int* in_sizes, int n_in,
                              void* d_out, int out_size) {
    const float* emb   = (const float*)d_in[0];
    const int*   eu    = (const int*)d_in[1];
    const int*   ei    = (const int*)d_in[2];
    const int*   users = (const int*)d_in[3];
    const int*   pos   = (const int*)d_in[4];
    const int*   neg   = (const int*)d_in[5];
    float* out = (float*)d_out;
    (void)in_sizes; (void)n_in; (void)out_size;

    // zero degrees via async memset (capture-legal, no extra kernel)
    void* deg_ptr = nullptr;
    cudaGetSymbolAddress(&deg_ptr, g_deg);
    cudaMemsetAsync(deg_ptr, 0, N_NODES * sizeof(int));

    k_count  <<<(N_INTER / 4 + T - 1) / T, T>>>(eu, ei);
    k_scan1  <<<SCAN_NBLK, SCAN_T>>>();
    k_scan2  <<<1, 256>>>();
    k_scan3  <<<(N_NODES + T - 1) / T, T>>>();
    k_fill_h0<<<FILL_BLOCKS + H0_BLOCKS, T>>>(eu, ei, emb);

    const int GPB = T / 8;                               // node-groups per block
    k_prop<1><<<(N_NODES + GPB - 1) / GPB, T>>>();
    k_prop<2><<<(N_NODES + GPB - 1) / GPB, T>>>();

    k_tail<<<OUT3_BLOCKS + L2_BLOCKS, T>>>(users, pos, neg, emb, out);
}

// round 8
// speedup vs baseline: 4.2772x; 1.1041x over previous
#include <cuda_runtime.h>
#include <cuda_fp16.h>

#define N_USERS 100000
#define N_ITEMS 50000
#define N_NODES (N_USERS + N_ITEMS)
#define EMB_DIM 64
#define N_INTER 1500000
#define BATCH 4096

#define CAP 96                                   // per-node edge bucket capacity
#define T 256
#define H0_ELEMS (N_NODES * (EMB_DIM / 2))       // half2 count
#define OUT3_BLOCKS (3 * BATCH / (T / 8))        // 384
#define L2_BLOCKS (BATCH / (T / 8))              // 128

// ---- scratch: __device__ globals (no allocation allowed) ----
__device__ __half2 g_h0[N_NODES * EMB_DIM / 2];  // fp16 gather shadows (128B/row)
__device__ __half2 g_h1[N_NODES * EMB_DIM / 2];
__device__ __half2 g_h2[N_NODES * EMB_DIM / 2];
__device__ int     g_col[N_NODES * CAP];         // padded-bucket CSR: sources
__device__ int     g_cur[N_NODES];               // fill cursors (end = final cur)
__device__ float   g_dinv [N_NODES];             // deg^-1/2 (1 if deg==0)
__device__ float   g_dinv2[N_NODES];

// ---------------- cursor init: cur[i] = i*CAP ----------------
__global__ void k_iota() {
    int i = blockIdx.x * blockDim.x + threadIdx.x;
    if (i < N_NODES) g_cur[i] = i * CAP;
}

// ---------------- edge fill into padded buckets (int4: 4 edges/thread) -----
__global__ void k_fill(const int* __restrict__ eu, const int* __restrict__ ei) {
    int t = blockIdx.x * blockDim.x + threadIdx.x;
    if (t >= N_INTER / 4) return;
    int4 u4 = ((const int4*)eu)[t];
    int4 i4 = ((const int4*)ei)[t];
    int u, v, p;
    u = u4.x; v = N_USERS + i4.x;
    p = atomicAdd(&g_cur[v], 1); g_col[p] = u;
    p = atomicAdd(&g_cur[u], 1); g_col[p] = v;
    u = u4.y; v = N_USERS + i4.y;
    p = atomicAdd(&g_cur[v], 1); g_col[p] = u;
    p = atomicAdd(&g_cur[u], 1); g_col[p] = v;
    u = u4.z; v = N_USERS + i4.z;
    p = atomicAdd(&g_cur[v], 1); g_col[p] = u;
    p = atomicAdd(&g_cur[u], 1); g_col[p] = v;
    u = u4.w; v = N_USERS + i4.w;
    p = atomicAdd(&g_cur[v], 1); g_col[p] = u;
    p = atomicAdd(&g_cur[u], 1); g_col[p] = v;
}

// ---------------- fused: dinv/dinv2 from cursors + h0 = fp16(dinv ⊙ emb) ---
// one thread per half2 element; thread j==0 of each node also writes dinv.
__global__ void k_h0dinv(const float* __restrict__ emb) {
    int i = blockIdx.x * blockDim.x + threadIdx.x;
    if (i >= H0_ELEMS) return;
    int node = i >> 5;                           // EMB_DIM/2 == 32 half2/row
    int deg = g_cur[node] - node * CAP;          // broadcast load per node
    float r = (deg > 0) ? rsqrtf((float)deg) : 1.0f;
    if ((i & 31) == 0) {
        g_dinv[node] = r;
        g_dinv2[node] = r * r;
    }
    float2 v = ((const float2*)emb)[i];
    g_h0[i] = __floats2half2_rn(v.x * r, v.y * r);
}

// ---- accumulate one 16B fp16 chunk into 8 fp32 sums ----
__device__ __forceinline__ void acc16(float acc[8], uint4 raw) {
    float2 f0 = __half22float2(*(__half2*)&raw.x);
    float2 f1 = __half22float2(*(__half2*)&raw.y);
    float2 f2 = __half22float2(*(__half2*)&raw.z);
    float2 f3 = __half22float2(*(__half2*)&raw.w);
    acc[0] += f0.x; acc[1] += f0.y;
    acc[2] += f1.x; acc[3] += f1.y;
    acc[4] += f2.x; acc[5] += f2.y;
    acc[6] += f3.x; acc[7] += f3.y;
}

// ---- gather: 8-lane group sums all neighbor rows; lane j owns 16B chunk j ----
__device__ __forceinline__ void gather_node(const __half2* __restrict__ hin,
                                            int s, int e, int j, float acc[8]) {
    #pragma unroll
    for (int k = 0; k < 8; k++) acc[k] = 0.f;
    #pragma unroll 8
    for (int p = s; p < e; p++) {
        int src = g_col[p];                    // group-uniform broadcast load
        uint4 raw = ((const uint4*)(hin + (size_t)src * 32))[j];
        acc16(acc, raw);
    }
}

// ---------------- layers 1 & 2: 4 nodes/warp, 8 lanes/node ----------------
template <int LAYER>
__global__ void k_prop() {
    const __half2* __restrict__ hin  = (LAYER == 1) ? g_h0 : g_h1;
    __half2* __restrict__       hout = (LAYER == 1) ? g_h1 : g_h2;

    int grp = blockIdx.x * (blockDim.x >> 3) + (threadIdx.x >> 3);  // node id
    if (grp >= N_NODES) return;
    int j = threadIdx.x & 7;          // 16B chunk within 128B row

    int s = grp * CAP;
    int e = g_cur[grp];

    float acc[8];
    gather_node(hin, s, e, j, acc);

    float d2 = g_dinv2[grp];
    uint4 packed;
    __half2 h0v = __floats2half2_rn(acc[0] * d2, acc[1] * d2);
    __half2 h1v = __floats2half2_rn(acc[2] * d2, acc[3] * d2);
    __half2 h2v = __floats2half2_rn(acc[4] * d2, acc[5] * d2);
    __half2 h3v = __floats2half2_rn(acc[6] * d2, acc[7] * d2);
    packed.x = *(unsigned*)&h0v; packed.y = *(unsigned*)&h1v;
    packed.z = *(unsigned*)&h2v; packed.w = *(unsigned*)&h3v;
    ((uint4*)(hout + (size_t)grp * 32))[j] = packed;
}

// ---------------- tail: out3 (layer-3 on demand) + l2 norms, one launch ----
__global__ void k_tail(const int* __restrict__ users,
                       const int* __restrict__ pos,
                       const int* __restrict__ neg,
                       const float* __restrict__ emb,
                       float* __restrict__ out) {
    int j = threadIdx.x & 7;
    if (blockIdx.x < OUT3_BLOCKS) {
        // ---- out3: one 8-lane group per (t, b) ----
        int id = blockIdx.x * (blockDim.x >> 3) + (threadIdx.x >> 3);
        int t = id / BATCH;
        int b = id - t * BATCH;
        int r = (t == 0) ? users[b]
              : (t == 1) ? N_USERS + pos[b]
                         : N_USERS + neg[b];

        int s = r * CAP;
        int e = g_cur[r];

        float acc[8];
        gather_node(g_h2, s, e, j, acc);       // layer-3 neighbor sum

        float d2 = g_dinv2[r];
        float inv = 1.0f / g_dinv[r];          // = sqrt(deg) (1 if deg==0)

        uint4 rh1 = ((const uint4*)(g_h1 + (size_t)r * 32))[j];
        uint4 rh2 = ((const uint4*)(g_h2 + (size_t)r * 32))[j];
        float h1v[8], h2v[8];
        {
            float2 f;
            f = __half22float2(*(__half2*)&rh1.x); h1v[0] = f.x; h1v[1] = f.y;
            f = __half22float2(*(__half2*)&rh1.y); h1v[2] = f.x; h1v[3] = f.y;
            f = __half22float2(*(__half2*)&rh1.z); h1v[4] = f.x; h1v[5] = f.y;
            f = __half22float2(*(__half2*)&rh1.w); h1v[6] = f.x; h1v[7] = f.y;
            f = __half22float2(*(__half2*)&rh2.x); h2v[0] = f.x; h2v[1] = f.y;
            f = __half22float2(*(__half2*)&rh2.y); h2v[2] = f.x; h2v[3] = f.y;
            f = __half22float2(*(__half2*)&rh2.z); h2v[4] = f.x; h2v[5] = f.y;
            f = __half22float2(*(__half2*)&rh2.w); h2v[6] = f.x; h2v[7] = f.y;
        }
        const float4* er = (const float4*)(emb + (size_t)r * EMB_DIM);
        float4 e0 = er[2 * j];
        float4 e1 = er[2 * j + 1];
        float ev[8] = {e0.x, e0.y, e0.z, e0.w, e1.x, e1.y, e1.z, e1.w};

        float res[8];
        #pragma unroll
        for (int k = 0; k < 8; k++)
            res[k] = 0.25f * (ev[k] + (h1v[k] + h2v[k] + acc[k] * d2) * inv);

        float4* orow = (float4*)(out + ((size_t)t * BATCH + b) * EMB_DIM);
        orow[2 * j]     = make_float4(res[0], res[1], res[2], res[3]);
        orow[2 * j + 1] = make_float4(res[4], res[5], res[6], res[7]);
    } else {
        // ---- l2: one 8-lane group per b ----
        int b = (blockIdx.x - OUT3_BLOCKS) * (blockDim.x >> 3) + (threadIdx.x >> 3);
        if (b >= BATCH) return;

        int rows[3];
        rows[0] = users[b];
        rows[1] = N_USERS + pos[b];
        rows[2] = N_USERS + neg[b];

        float l2 = 0.f;
        #pragma unroll
        for (int t = 0; t < 3; t++) {
            const float4* er = (const float4*)(emb + (size_t)rows[t] * EMB_DIM);
            float4 a = er[2 * j];
            float4 c = er[2 * j + 1];
            l2 += a.x * a.x + a.y * a.y + a.z * a.z + a.w * a.w
                + c.x * c.x + c.y * c.y + c.z * c.z + c.w * c.w;
        }
        #pragma unroll
        for (int off = 4; off; off >>= 1)
            l2 += __shfl_down_sync(0xffffffffu, l2, off, 8);
        if (j == 0) out[(size_t)3 * BATCH * EMB_DIM + b] = l2;
    }
}

// ---------------- launcher ----------------
extern "C" void kernel_launch(void* const* d_in, const int* in_sizes, int n_in,
                              void* d_out, int out_size) {
    const float* emb   = (const float*)d_in[0];
    const int*   eu    = (const int*)d_in[1];
    const int*   ei    = (const int*)d_in[2];
    const int*   users = (const int*)d_in[3];
    const int*   pos   = (const int*)d_in[4];
    const int*   neg   = (const int*)d_in[5];
    float* out = (float*)d_out;
    (void)in_sizes; (void)n_in; (void)out_size;

    k_iota  <<<(N_NODES + T - 1) / T, T>>>();
    k_fill  <<<(N_INTER / 4 + T - 1) / T, T>>>(eu, ei);
    k_h0dinv<<<(H0_ELEMS + T - 1) / T, T>>>(emb);

    const int GPB = T / 8;                               // node-groups per block
    k_prop<1><<<(N_NODES + GPB - 1) / GPB, T>>>();
    k_prop<2><<<(N_NODES + GPB - 1) / GPB, T>>>();

    k_tail<<<OUT3_BLOCKS + L2_BLOCKS, T>>>(users, pos, neg, emb, out);
}